// round 1
// baseline (speedup 1.0000x reference)
#include <cuda_runtime.h>

#define N_NODES 262144
#define C 64
#define K 16
#define NCLS 40

#define WARPS 4
#define NODES_PER_WARP 8
#define NODES_PER_BLOCK (WARPS * NODES_PER_WARP)
#define FSTRIDE 132   // 128 feat floats + 4 pad -> conflict-free phase-2 reads

// scratch (allocation-free rule: __device__ globals)
__device__ __align__(256) static float d_h[N_NODES * C];   // 64 MB, L2-resident working set
__device__ static float d_W[2 * C * NCLS];                 // fused [h|rel] -> logits weights
__device__ static float d_bf[NCLS];                        // fused bias
__device__ static int   d_idx64;                           // nbr_idx dtype flag

// ---------- packed f32x2 helpers (FFMA2) ----------
__device__ __forceinline__ unsigned long long pack2(float a, float b) {
    unsigned long long r;
    asm("mov.b64 %0, {%1,%2};" : "=l"(r) : "f"(a), "f"(b));
    return r;
}
__device__ __forceinline__ void unpack2(unsigned long long v, float& a, float& b) {
    asm("mov.b64 {%0,%1}, %2;" : "=f"(a), "=f"(b) : "l"(v));
}
__device__ __forceinline__ void ffma2(unsigned long long& d, unsigned long long a,
                                      unsigned long long b) {
    asm("fma.rn.f32x2 %0, %1, %2, %0;" : "+l"(d) : "l"(a), "l"(b));
}

// ---------- kernel 0: detect whether nbr_idx is int64 or int32 ----------
// Values are in [0, 262144). If stored as int64 (LE), every odd 32-bit word is 0.
// If int32, odd words are random indices (zero w.p. 2^-18 each; 256 checks => safe).
__global__ void detect_idx_kernel(const unsigned int* __restrict__ w) {
    __shared__ int any;
    if (threadIdx.x == 0) any = 0;
    __syncthreads();
    if (w[2 * threadIdx.x + 1] != 0u) any = 1;
    __syncthreads();
    if (threadIdx.x == 0) d_idx64 = (any ? 0 : 1);
}

// ---------- kernel 1: CPE depthwise conv (kernel 3 over node dim) + residual ----------
__global__ void cpe_kernel(const float4* __restrict__ x4,
                           const float* __restrict__ cw,   // [C,3]
                           const float* __restrict__ cb) { // [C]
    int gid = blockIdx.x * blockDim.x + threadIdx.x;
    if (gid >= N_NODES * (C / 4)) return;
    int n = gid >> 4;
    int q = gid & 15;
    float4 xc = x4[gid];
    float4 xm = make_float4(0.f, 0.f, 0.f, 0.f);
    float4 xp = make_float4(0.f, 0.f, 0.f, 0.f);
    if (n > 0)            xm = x4[gid - (C / 4)];
    if (n < N_NODES - 1)  xp = x4[gid + (C / 4)];
    int c0 = q * 4;
    float4 r;
    r.x = xc.x + (xm.x * cw[(c0 + 0) * 3 + 0] + xc.x * cw[(c0 + 0) * 3 + 1] + xp.x * cw[(c0 + 0) * 3 + 2] + cb[c0 + 0]);
    r.y = xc.y + (xm.y * cw[(c0 + 1) * 3 + 0] + xc.y * cw[(c0 + 1) * 3 + 1] + xp.y * cw[(c0 + 1) * 3 + 2] + cb[c0 + 1]);
    r.z = xc.z + (xm.z * cw[(c0 + 2) * 3 + 0] + xc.z * cw[(c0 + 2) * 3 + 1] + xp.z * cw[(c0 + 2) * 3 + 2] + cb[c0 + 2]);
    r.w = xc.w + (xm.w * cw[(c0 + 3) * 3 + 0] + xc.w * cw[(c0 + 3) * 3 + 1] + xp.w * cw[(c0 + 3) * 3 + 2] + cb[c0 + 3]);
    reinterpret_cast<float4*>(d_h)[gid] = r;
}

// ---------- kernel 2: fuse grapher projection into the classifier head ----------
// logits = h @ W[0:64] + rel @ W[64:128] + bf, where
//   W[c][j]   = (c<64 ? o_w[c][j] : 0) + sum_d g_w[c][d] * o_w[d][j]
//   bf[j]     = o_b[j] + sum_d g_b[d] * o_w[d][j]
__global__ void fuse_w_kernel(const float* __restrict__ gw,  // [128,64]
                              const float* __restrict__ gb,  // [64]
                              const float* __restrict__ ow,  // [64,40]
                              const float* __restrict__ ob) {// [40]
    int t = blockIdx.x * blockDim.x + threadIdx.x;
    if (t < 2 * C * NCLS) {
        int c = t / NCLS, j = t % NCLS;
        float acc = (c < C) ? ow[c * NCLS + j] : 0.f;
        #pragma unroll 8
        for (int d = 0; d < C; ++d) acc += gw[c * C + d] * ow[d * NCLS + j];
        d_W[t] = acc;
    } else if (t < 2 * C * NCLS + NCLS) {
        int j = t - 2 * C * NCLS;
        float acc = ob[j];
        for (int d = 0; d < C; ++d) acc += gb[d] * ow[d * NCLS + j];
        d_bf[j] = acc;
    }
}

// ---------- kernel 3: gather + max-relative + fused GEMM + log_softmax ----------
__global__ __launch_bounds__(WARPS * 32) void main_kernel(const void* __restrict__ nbr,
                                                          float* __restrict__ out) {
    __shared__ __align__(16) float sW[2 * C * NCLS];
    __shared__ float sBF[NCLS];
    __shared__ __align__(16) float sFeat[WARPS * NODES_PER_WARP * FSTRIDE];

    const float* __restrict__ H = d_h;
    const int tid = threadIdx.x;

    // stage fused weights into shared
    for (int i = tid; i < 2 * C * NCLS; i += WARPS * 32) sW[i] = d_W[i];
    if (tid < NCLS) sBF[tid] = d_bf[tid];

    const int warp = tid >> 5, lane = tid & 31;
    const int nodeBase = blockIdx.x * NODES_PER_BLOCK + warp * NODES_PER_WARP;
    float* feat = sFeat + warp * NODES_PER_WARP * FSTRIDE;
    const int is64 = d_idx64;

    // ---- phase 1: gather 16 neighbors per node, running channel-wise max ----
    // lane owns channels (2*lane, 2*lane+1) as float2
    #pragma unroll 1
    for (int i = 0; i < NODES_PER_WARP; ++i) {
        const int n = nodeBase + i;
        int myj = 0;
        if (lane < K) {
            if (is64) myj = (int)((const long long*)nbr)[(size_t)n * K + lane];
            else      myj = ((const int*)nbr)[n * K + lane];
        }
        const float2 hv = *(const float2*)(H + n * C + 2 * lane);
        float2 mv = make_float2(-3.402823466e38f, -3.402823466e38f);
        #pragma unroll
        for (int k = 0; k < K; ++k) {
            const int j = __shfl_sync(0xffffffffu, myj, k);
            const float2 xv = __ldg((const float2*)(H + j * C + 2 * lane));
            mv.x = fmaxf(mv.x, xv.x);
            mv.y = fmaxf(mv.y, xv.y);
        }
        *(float2*)(feat + i * FSTRIDE + 2 * lane) = hv;                     // feat[0:64)  = h
        float2 rv = make_float2(mv.x - hv.x, mv.y - hv.y);                  // max(xj)-h == max(xj-h)
        *(float2*)(feat + i * FSTRIDE + C + 2 * lane) = rv;                 // feat[64:128) = rel
    }
    __syncthreads();  // sW staging + (warp-local) feat

    // ---- phase 2: per-node [1,128] @ [128,40] with packed FFMA2 ----
    // lane -> (node-group ng = lane/4, pair-group pg = lane%4); class pairs p = pg*5+t
    const int ng = lane >> 2, pg = lane & 3;
    const float* fv = feat + ng * FSTRIDE;
    unsigned long long acc[5];
    #pragma unroll
    for (int t = 0; t < 5; ++t) {
        const int p = pg * 5 + t;
        acc[t] = pack2(sBF[2 * p], sBF[2 * p + 1]);
    }
    #pragma unroll 4
    for (int c = 0; c < 2 * C; ++c) {
        const float v = fv[c];
        const unsigned long long vv = pack2(v, v);
        const float* wrow = sW + c * NCLS + pg * 10;
        #pragma unroll
        for (int t = 0; t < 5; ++t) {
            const unsigned long long w = *(const unsigned long long*)(wrow + 2 * t);
            ffma2(acc[t], vv, w);
        }
    }

    // ---- log_softmax over 40 classes (reduce across the 4 lanes of each node-group) ----
    float lg[10];
    #pragma unroll
    for (int t = 0; t < 5; ++t) unpack2(acc[t], lg[2 * t], lg[2 * t + 1]);
    float m = lg[0];
    #pragma unroll
    for (int i = 1; i < 10; ++i) m = fmaxf(m, lg[i]);
    m = fmaxf(m, __shfl_xor_sync(0xffffffffu, m, 1));
    m = fmaxf(m, __shfl_xor_sync(0xffffffffu, m, 2));
    float s = 0.f;
    #pragma unroll
    for (int i = 0; i < 10; ++i) s += __expf(lg[i] - m);
    s += __shfl_xor_sync(0xffffffffu, s, 1);
    s += __shfl_xor_sync(0xffffffffu, s, 2);
    const float lse = m + __logf(s);

    const int n = nodeBase + ng;
    float* op = out + (size_t)n * NCLS + pg * 10;
    #pragma unroll
    for (int t = 0; t < 5; ++t) {
        float2 o;
        o.x = lg[2 * t]     - lse;
        o.y = lg[2 * t + 1] - lse;
        *(float2*)(op + 2 * t) = o;
    }
}

extern "C" void kernel_launch(void* const* d_in, const int* in_sizes, int n_in,
                              void* d_out, int out_size) {
    const float* x  = (const float*)d_in[0];
    const void*  nb = d_in[1];
    const float* cw = (const float*)d_in[2];
    const float* cb = (const float*)d_in[3];
    const float* gw = (const float*)d_in[4];
    const float* gb = (const float*)d_in[5];
    const float* ow = (const float*)d_in[6];
    const float* ob = (const float*)d_in[7];
    float* out = (float*)d_out;

    detect_idx_kernel<<<1, 256>>>((const unsigned int*)nb);
    cpe_kernel<<<(N_NODES * (C / 4) + 255) / 256, 256>>>((const float4*)x, cw, cb);
    fuse_w_kernel<<<(2 * C * NCLS + NCLS + 127) / 128, 128>>>(gw, gb, ow, ob);
    main_kernel<<<N_NODES / NODES_PER_BLOCK, WARPS * 32>>>(nb, out);
}